// round 1
// baseline (speedup 1.0000x reference)
#include <cuda_runtime.h>

// LIF forward: X [B, T, N] fp32 -> spikes [B, T, N] fp32
// mem_{t} = (mem_{t-1} + x_t) * 0.5 ; spike = mem > 1 ; mem = spike ? 0 : mem
// Fixed shape: T=32, N=8192. B derived from input size.

#define T_STEPS 32
#define N_DIM   8192
#define N4      (N_DIM / 4)   // 2048 float4 per row

__global__ __launch_bounds__(256)
void lif_kernel(const float4* __restrict__ X, float4* __restrict__ out, int total_quads) {
    int idx = blockIdx.x * blockDim.x + threadIdx.x;
    if (idx >= total_quads) return;

    int b  = idx / N4;
    int n4 = idx - b * N4;

    const float4* __restrict__ xp = X   + (size_t)b * (T_STEPS * N4) + n4;
    float4* __restrict__       op = out + (size_t)b * (T_STEPS * N4) + n4;

    float mx = 0.f, my = 0.f, mz = 0.f, mw = 0.f;

    #pragma unroll
    for (int t = 0; t < T_STEPS; t++) {
        float4 x = xp[(size_t)t * N4];

        mx = (mx + x.x) * 0.5f;
        my = (my + x.y) * 0.5f;
        mz = (mz + x.z) * 0.5f;
        mw = (mw + x.w) * 0.5f;

        float4 s;
        s.x = (mx > 1.0f) ? 1.0f : 0.0f;
        s.y = (my > 1.0f) ? 1.0f : 0.0f;
        s.z = (mz > 1.0f) ? 1.0f : 0.0f;
        s.w = (mw > 1.0f) ? 1.0f : 0.0f;

        // hard reset where spiked
        mx = (s.x > 0.f) ? 0.0f : mx;
        my = (s.y > 0.f) ? 0.0f : my;
        mz = (s.z > 0.f) ? 0.0f : mz;
        mw = (s.w > 0.f) ? 0.0f : mw;

        op[(size_t)t * N4] = s;
    }
}

extern "C" void kernel_launch(void* const* d_in, const int* in_sizes, int n_in,
                              void* d_out, int out_size) {
    const float4* X = (const float4*)d_in[0];
    float4* out = (float4*)d_out;

    int total_elems = in_sizes[0];                 // B*T*N
    int B = total_elems / (T_STEPS * N_DIM);
    int total_quads = B * N4;                      // threads: one per (b, n/4)

    int threads = 256;
    int blocks = (total_quads + threads - 1) / threads;
    lif_kernel<<<blocks, threads>>>(X, out, total_quads);
}